// round 2
// baseline (speedup 1.0000x reference)
#include <cuda_runtime.h>
#include <math.h>

#define TT 50
#define HH 256
#define NCTA 16
#define NW 16
#define THREADS 512

// scratch (no allocations allowed)
__device__ float g_pre[TT * 768];
__device__ float g_lout[TT * HH];

__device__ __forceinline__ float eluf(float x) { return x > 0.f ? x : expm1f(x); }
__device__ __forceinline__ float sigm(float x) { return 1.f / (1.f + expf(-x)); }

__device__ __forceinline__ float warp_sum(float v) {
#pragma unroll
    for (int m = 16; m; m >>= 1) v += __shfl_xor_sync(0xffffffffu, v, m);
    return v;
}

__device__ __forceinline__ void st_cluster(float* p, int rank, float v) {
    unsigned a = (unsigned)__cvta_generic_to_shared(p);
    unsigned r;
    asm volatile("mapa.shared::cluster.u32 %0, %1, %2;" : "=r"(r) : "r"(a), "r"(rank));
    asm volatile("st.shared::cluster.f32 [%0], %1;" :: "r"(r), "f"(v));
}

__device__ __forceinline__ float dot8(float4 wa, float4 wb, float4 xa, float4 xb) {
    return wa.x*xa.x + wa.y*xa.y + wa.z*xa.z + wa.w*xa.w
         + wb.x*xb.x + wb.y*xb.y + wb.z*xb.z + wb.w*xb.w;
}

// ---------------------------------------------------------------------------
// Pre-kernel: f_v = elu(v0@W1v.T + b1v), f_m = elu(m0@W1m.T + b1m),
// g_pre[t][j] = Wih_low[j, :256] @ [f_v; f_m] + bih_low[j] + (bhh_low[j] for r,z rows)
// ---------------------------------------------------------------------------
__global__ void pre_kernel(const float* __restrict__ v0, const float* __restrict__ m0,
                           const float* __restrict__ W1v, const float* __restrict__ b1v,
                           const float* __restrict__ W1m, const float* __restrict__ b1m,
                           const float* __restrict__ Wih_low, const float* __restrict__ bih_low,
                           const float* __restrict__ bhh_low)
{
    __shared__ float sx[256];
    int t = blockIdx.x, tid = threadIdx.x;
    if (tid < 128) {
        const float* vr = v0 + t * 768;
        const float* wr = W1v + tid * 768;
        float acc = b1v[tid];
        for (int k = 0; k < 768; k += 4) {
            float4 a = *(const float4*)(vr + k);
            float4 b = *(const float4*)(wr + k);
            acc += a.x*b.x + a.y*b.y + a.z*b.z + a.w*b.w;
        }
        sx[tid] = eluf(acc);
    } else {
        int f = tid - 128;
        float acc = b1m[f] + m0[t * 2] * W1m[f * 2] + m0[t * 2 + 1] * W1m[f * 2 + 1];
        sx[tid] = eluf(acc);
    }
    __syncthreads();
#pragma unroll
    for (int rr = 0; rr < 3; rr++) {
        int j = tid + rr * 256;
        const float* wr = Wih_low + j * 512;
        float acc = bih_low[j] + (j < 512 ? bhh_low[j] : 0.f);
        for (int k = 0; k < 256; k += 4) {
            float4 b = *(const float4*)(wr + k);
            float4 a = *(const float4*)(sx + k);
            acc += a.x*b.x + a.y*b.y + a.z*b.z + a.w*b.w;
        }
        g_pre[t * 768 + j] = acc;
    }
}

// ---------------------------------------------------------------------------
// Recurrent kernel: persistent 16-CTA cluster, one hidden unit per warp.
// Smem-resident: W_lh2 (= Wih_low[:,256:512]) and Wih_high.
// Register-resident: Whh_low, Whh_high.
// Split cluster barriers with independent matvecs scheduled in the gap.
// ---------------------------------------------------------------------------
__global__ void __launch_bounds__(THREADS, 1) gru_kernel(
    const float* __restrict__ Wih_low, const float* __restrict__ Whh_low,
    const float* __restrict__ bhh_low,
    const float* __restrict__ Wih_high, const float* __restrict__ Whh_high,
    const float* __restrict__ bih_high, const float* __restrict__ bhh_high)
{
    extern __shared__ float smem[];
    float* sW  = smem;                  // [NW][2 mats][3 rows][256]
    float* sH1 = smem + NW * 1536;      // [2][256] double-buffered
    float* sH2 = sH1 + 2 * 256;         // [2][256]

    const int tid = threadIdx.x;
    const int w = tid >> 5, l = tid & 31;
    unsigned rank;
    asm("mov.u32 %0, %%cluster_ctarank;" : "=r"(rank));
    const int i = (int)rank * NW + w;     // global hidden index 0..255
    const int c0 = 4 * l, c1 = 128 + 4 * l;
    float* wb = sW + w * 1536;

    // zero both parities of h1/h2 (512 threads cover 2*256 each)
    sH1[tid] = 0.f;
    sH2[tid] = 0.f;

    const int j0 = i, j1 = 256 + i, j2 = 512 + i;
    const int jj[3] = { j0, j1, j2 };

    float4 wlh[3][2], whh[3][2];
#pragma unroll
    for (int g = 0; g < 3; g++) {
        int j = jj[g];
        *(float4*)(wb + g * 256 + c0)       = *(const float4*)(Wih_low + j * 512 + 256 + c0);
        *(float4*)(wb + g * 256 + c1)       = *(const float4*)(Wih_low + j * 512 + 256 + c1);
        *(float4*)(wb + 768 + g * 256 + c0) = *(const float4*)(Wih_high + j * 256 + c0);
        *(float4*)(wb + 768 + g * 256 + c1) = *(const float4*)(Wih_high + j * 256 + c1);
        wlh[g][0] = *(const float4*)(Whh_low + j * 256 + c0);
        wlh[g][1] = *(const float4*)(Whh_low + j * 256 + c1);
        whh[g][0] = *(const float4*)(Whh_high + j * 256 + c0);
        whh[g][1] = *(const float4*)(Whh_high + j * 256 + c1);
    }

    const float bLn = bhh_low[512 + i];                      // gh_n bias (low)
    const float cAr = bih_high[i] + bhh_high[i];             // high r: both biases fold
    const float cAz = bih_high[256 + i] + bhh_high[256 + i]; // high z
    const float cAn = bih_high[512 + i];                     // high n: gi bias
    const float cBn = bhh_high[512 + i];                     // high n: gh bias

    __syncthreads();
    asm volatile("barrier.cluster.arrive.aligned;" ::: "memory");
    asm volatile("barrier.cluster.wait.aligned;" ::: "memory");

    // Whh_low @ h1 with h1 = 0  ->  0
    float Blr = 0.f, Blz = 0.f, Bln = 0.f;
    float pr = g_pre[j0], pz = g_pre[j1], pn = g_pre[j2];
    int p = 0;

    for (int t = 0; t < TT; t++) {
        // ================= phase 1: low GRU ==========================
        float4 h2a = *(const float4*)(sH2 + p * 256 + c0);
        float4 h2b = *(const float4*)(sH2 + p * 256 + c1);
        float A0, A1, A2v;
        {
            float4 wa0 = *(const float4*)(wb + 0 * 256 + c0);
            float4 wb0 = *(const float4*)(wb + 0 * 256 + c1);
            float4 wa1 = *(const float4*)(wb + 1 * 256 + c0);
            float4 wb1 = *(const float4*)(wb + 1 * 256 + c1);
            float4 wa2 = *(const float4*)(wb + 2 * 256 + c0);
            float4 wb2 = *(const float4*)(wb + 2 * 256 + c1);
            A0 = dot8(wa0, wb0, h2a, h2b);
            A1 = dot8(wa1, wb1, h2a, h2b);
            A2v = dot8(wa2, wb2, h2a, h2b);
        }
        float Ar = warp_sum(A0), Az = warp_sum(A1), An = warp_sum(A2v);
        float h1old = sH1[p * 256 + i];
        float r = sigm(pr + Ar + Blr);
        float z = sigm(pz + Az + Blz);
        float n = tanhf(pn + An + r * (Bln + bLn));
        float h1n = (1.f - z) * n + z * h1old;

        if (l < NCTA) st_cluster(sH1 + (p ^ 1) * 256 + i, l, h1n);
        if (l == 16) g_lout[t * 256 + i] = h1n;
        asm volatile("barrier.cluster.arrive.aligned;" ::: "memory");

        // hidden work: B_high = Whh_high @ h2[p] (register weights, h2 regs reused)
        float Bhr = warp_sum(dot8(whh[0][0], whh[0][1], h2a, h2b));
        float Bhz = warp_sum(dot8(whh[1][0], whh[1][1], h2a, h2b));
        float Bhn = warp_sum(dot8(whh[2][0], whh[2][1], h2a, h2b));

        asm volatile("barrier.cluster.wait.aligned;" ::: "memory");

        // ================= phase 2: high GRU =========================
        float4 h1a = *(const float4*)(sH1 + (p ^ 1) * 256 + c0);
        float4 h1b = *(const float4*)(sH1 + (p ^ 1) * 256 + c1);
        float G0, G1, G2;
        {
            float4 wa0 = *(const float4*)(wb + 768 + 0 * 256 + c0);
            float4 wb0 = *(const float4*)(wb + 768 + 0 * 256 + c1);
            float4 wa1 = *(const float4*)(wb + 768 + 1 * 256 + c0);
            float4 wb1 = *(const float4*)(wb + 768 + 1 * 256 + c1);
            float4 wa2 = *(const float4*)(wb + 768 + 2 * 256 + c0);
            float4 wb2 = *(const float4*)(wb + 768 + 2 * 256 + c1);
            G0 = dot8(wa0, wb0, h1a, h1b);
            G1 = dot8(wa1, wb1, h1a, h1b);
            G2 = dot8(wa2, wb2, h1a, h1b);
        }
        float A2r = warp_sum(G0), A2z = warp_sum(G1), A2n = warp_sum(G2);
        float h2old = sH2[p * 256 + i];
        float r2 = sigm(cAr + A2r + Bhr);
        float z2 = sigm(cAz + A2z + Bhz);
        float n2 = tanhf(cAn + A2n + r2 * (Bhn + cBn));
        float h2n = (1.f - z2) * n2 + z2 * h2old;

        if (l < NCTA) st_cluster(sH2 + (p ^ 1) * 256 + i, l, h2n);
        asm volatile("barrier.cluster.arrive.aligned;" ::: "memory");

        // hidden work: next step's B_low = Whh_low @ h1[p^1] (h1 regs reused)
        Blr = warp_sum(dot8(wlh[0][0], wlh[0][1], h1a, h1b));
        Blz = warp_sum(dot8(wlh[1][0], wlh[1][1], h1a, h1b));
        Bln = warp_sum(dot8(wlh[2][0], wlh[2][1], h1a, h1b));
        if (t + 1 < TT) {
            pr = __ldg(g_pre + (t + 1) * 768 + j0);
            pz = __ldg(g_pre + (t + 1) * 768 + j1);
            pn = __ldg(g_pre + (t + 1) * 768 + j2);
        }

        asm volatile("barrier.cluster.wait.aligned;" ::: "memory");
        p ^= 1;
    }
}

// ---------------------------------------------------------------------------
// Post-kernel: v_n = sigmoid(elu(h1[:, :128]) @ W2v.T + b2v)   (T,768)
//              m_n = tanh   (elu(h1[:,128:256]) @ W2m.T + b2m) (T,2)
// Output layout: [v_n flat (T*768) | m_n flat (T*2)]
// ---------------------------------------------------------------------------
__global__ void post_kernel(const float* __restrict__ W2v, const float* __restrict__ b2v,
                            const float* __restrict__ W2m, const float* __restrict__ b2m,
                            float* __restrict__ out)
{
    __shared__ float se[256];
    int t = blockIdx.x, tid = threadIdx.x;
    se[tid] = eluf(g_lout[t * 256 + tid]);
    __syncthreads();
#pragma unroll
    for (int rr = 0; rr < 3; rr++) {
        int o = tid + rr * 256;
        const float* wr = W2v + o * 128;
        float acc = b2v[o];
        for (int k = 0; k < 128; k += 4) {
            float4 b = *(const float4*)(wr + k);
            float4 a = *(const float4*)(se + k);
            acc += a.x*b.x + a.y*b.y + a.z*b.z + a.w*b.w;
        }
        out[t * 768 + o] = sigm(acc);
    }
    // m head: W2m is (MIN=2, MF=128). m_n[t][o] = tanh(b2m[o] + elu_h[128:256] . W2m[o])
    if (tid < 2) {
        const float* wr = W2m + tid * 128;
        float acc = b2m[tid];
        for (int k = 0; k < 128; k += 4) {
            float4 b = *(const float4*)(wr + k);
            float4 a = *(const float4*)(se + 128 + k);
            acc += a.x*b.x + a.y*b.y + a.z*b.z + a.w*b.w;
        }
        out[TT * 768 + t * 2 + tid] = tanhf(acc);
    }
}

// ---------------------------------------------------------------------------
extern "C" void kernel_launch(void* const* d_in, const int* in_sizes, int n_in,
                              void* d_out, int out_size) {
    const float* v0       = (const float*)d_in[0];
    const float* m0       = (const float*)d_in[1];
    const float* W1v      = (const float*)d_in[2];
    const float* b1v      = (const float*)d_in[3];
    const float* W1m      = (const float*)d_in[4];
    const float* b1m      = (const float*)d_in[5];
    const float* Wih_low  = (const float*)d_in[6];
    const float* Whh_low  = (const float*)d_in[7];
    const float* bih_low  = (const float*)d_in[8];
    const float* bhh_low  = (const float*)d_in[9];
    const float* Wih_high = (const float*)d_in[10];
    const float* Whh_high = (const float*)d_in[11];
    const float* bih_high = (const float*)d_in[12];
    const float* bhh_high = (const float*)d_in[13];
    const float* W2v      = (const float*)d_in[14];
    const float* b2v      = (const float*)d_in[15];
    const float* W2m      = (const float*)d_in[16];
    const float* b2m      = (const float*)d_in[17];
    float* out = (float*)d_out;

    pre_kernel<<<TT, 256>>>(v0, m0, W1v, b1v, W1m, b1m, Wih_low, bih_low, bhh_low);

    const int SMEM = (NW * 1536 + 4 * 256) * (int)sizeof(float);  // 102400 B
    cudaFuncSetAttribute(gru_kernel, cudaFuncAttributeMaxDynamicSharedMemorySize, SMEM);
    cudaFuncSetAttribute(gru_kernel, cudaFuncAttributeNonPortableClusterSizeAllowed, 1);

    cudaLaunchConfig_t cfg = {};
    cfg.gridDim = dim3(NCTA, 1, 1);
    cfg.blockDim = dim3(THREADS, 1, 1);
    cfg.dynamicSmemBytes = SMEM;
    cfg.stream = 0;
    cudaLaunchAttribute attr[1];
    attr[0].id = cudaLaunchAttributeClusterDimension;
    attr[0].val.clusterDim.x = NCTA;
    attr[0].val.clusterDim.y = 1;
    attr[0].val.clusterDim.z = 1;
    cfg.attrs = attr;
    cfg.numAttrs = 1;
    cudaLaunchKernelEx(&cfg, gru_kernel, Wih_low, Whh_low, bhh_low,
                       Wih_high, Whh_high, bih_high, bhh_high);

    post_kernel<<<TT, 256>>>(W2v, b2v, W2m, b2m, out);
}